// round 12
// baseline (speedup 1.0000x reference)
#include <cuda_runtime.h>
#include <cuda_bf16.h>
#include <cstdint>

#define B_ 2
#define T_ 2048
#define D_ 1024
#define NH_ 16
#define KH_ 8
#define H_ 128

static constexpr float SCALE_ = 0.08838834764831845f;   // 128^-0.5
static constexpr float KMASK_ = -3.4028234663852886e38f;

// Scratch (device globals; no runtime allocation allowed)
__device__ float g_q[(size_t)B_ * NH_ * T_ * H_];   // [B][N][T][H] (tf32-rounded)
__device__ float g_k[(size_t)B_ * KH_ * T_ * H_];   // [B][K][S][H] (tf32-rounded)
__device__ float g_v[(size_t)B_ * KH_ * T_ * H_];   // [B][K][S][H] (tf32-rounded)
__device__ float g_o[(size_t)B_ * T_ * NH_ * H_];   // [B][T][N][H] (tf32-rounded)
__device__ int   g_pos[B_ * T_];
// tf32-rounded copies of inputs
__device__ float g_x [(size_t)B_ * T_ * D_];
__device__ float g_wq[(size_t)D_ * NH_ * H_];
__device__ float g_wk[(size_t)D_ * KH_ * H_];
__device__ float g_wv[(size_t)D_ * KH_ * H_];
__device__ float g_wo[(size_t)NH_ * H_ * D_];

// ---------------------------------------------------------------------------
__device__ __forceinline__ uint32_t f2tf32(float x) {
    uint32_t r;
    asm("cvt.rna.tf32.f32 %0, %1;" : "=r"(r) : "f"(x));
    return r;
}

__device__ __forceinline__ void mma_tf32(float* c,
                                         uint32_t a0, uint32_t a1, uint32_t a2, uint32_t a3,
                                         uint32_t b0, uint32_t b1) {
    asm volatile(
        "mma.sync.aligned.m16n8k8.row.col.f32.tf32.tf32.f32 "
        "{%0,%1,%2,%3}, {%4,%5,%6,%7}, {%8,%9}, {%0,%1,%2,%3};\n"
        : "+f"(c[0]), "+f"(c[1]), "+f"(c[2]), "+f"(c[3])
        : "r"(a0), "r"(a1), "r"(a2), "r"(a3), "r"(b0), "r"(b1));
}

__device__ __forceinline__ void cpa16(uint32_t saddr, const void* gptr) {
    asm volatile("cp.async.ca.shared.global [%0], [%1], 16;\n"
                 :: "r"(saddr), "l"(gptr));
}
__device__ __forceinline__ void cpa_commit() {
    asm volatile("cp.async.commit_group;\n" ::: "memory");
}
__device__ __forceinline__ void cpa_wait0() {
    asm volatile("cp.async.wait_group 0;\n" ::: "memory");
}
__device__ __forceinline__ void cpa_wait1() {
    asm volatile("cp.async.wait_group 1;\n" ::: "memory");
}

// ---------------------------------------------------------------------------
// Positions from segment ids.
// ---------------------------------------------------------------------------
__global__ __launch_bounds__(256) void pos_kernel(const int* __restrict__ seg) {
    int b = blockIdx.x;
    int tid = threadIdx.x;
    __shared__ int sred[256];

    int mv = -2147483647 - 1;
    for (int t = tid; t < T_; t += 256) mv = max(mv, seg[b * T_ + t]);
    sred[tid] = mv;
    __syncthreads();
    for (int st = 128; st > 0; st >>= 1) {
        if (tid < st) sred[tid] = max(sred[tid], sred[tid + st]);
        __syncthreads();
    }
    int maxv = sred[0];
    __syncthreads();

    int mi = 0x7fffffff;
    for (int t = tid; t < T_; t += 256)
        if (seg[b * T_ + t] == maxv) mi = min(mi, t);
    sred[tid] = mi;
    __syncthreads();
    for (int st = 128; st > 0; st >>= 1) {
        if (tid < st) sred[tid] = min(sred[tid], sred[tid + st]);
        __syncthreads();
    }
    int off = sred[0];

    for (int t = tid; t < T_; t += 256) {
        int s = seg[b * T_ + t];
        g_pos[b * T_ + t] = (s != 0) ? (t - off) : (1 << 30);
    }
}

// ---------------------------------------------------------------------------
// Round x to tf32 into g_x.
// ---------------------------------------------------------------------------
__global__ __launch_bounds__(256) void round_x_kernel(const float* __restrict__ src) {
    const int n4 = (B_ * T_ * D_) / 4;
    int i = blockIdx.x * 256 + threadIdx.x;
    int stride = gridDim.x * 256;
    for (; i < n4; i += stride) {
        float4 v = *(const float4*)(src + (size_t)i * 4);
        v.x = __uint_as_float(f2tf32(v.x));
        v.y = __uint_as_float(f2tf32(v.y));
        v.z = __uint_as_float(f2tf32(v.z));
        v.w = __uint_as_float(f2tf32(v.w));
        *(float4*)(g_x + (size_t)i * 4) = v;
    }
}

// ---------------------------------------------------------------------------
// Round all 4 weight tensors to tf32 (flat index over concat).
// ---------------------------------------------------------------------------
__global__ __launch_bounds__(256) void round_w_kernel(const float* __restrict__ wq,
                                                      const float* __restrict__ wk,
                                                      const float* __restrict__ wv,
                                                      const float* __restrict__ wo) {
    const int N4 = 1572864;
    int i = blockIdx.x * 256 + threadIdx.x;
    int stride = gridDim.x * 256;
    for (; i < N4; i += stride) {
        const float* src;
        float* dst;
        int j;
        if (i < 524288)       { src = wq; dst = g_wq; j = i; }
        else if (i < 786432)  { src = wk; dst = g_wk; j = i - 524288; }
        else if (i < 1048576) { src = wv; dst = g_wv; j = i - 786432; }
        else                  { src = wo; dst = g_wo; j = i - 1048576; }
        float4 v = *(const float4*)(src + (size_t)j * 4);
        v.x = __uint_as_float(f2tf32(v.x));
        v.y = __uint_as_float(f2tf32(v.y));
        v.z = __uint_as_float(f2tf32(v.z));
        v.w = __uint_as_float(f2tf32(v.w));
        *(float4*)(dst + (size_t)j * 4) = v;
    }
}

// ---------------------------------------------------------------------------
// QKV projection GEMM (tf32 mma, cp.async 2-stage, dyn smem 71,680B).
// ---------------------------------------------------------------------------
#define GEMM_SA_WORDS (2 * 128 * 36)
#define GEMM_SB_WORDS (2 * 32 * 136)
#define GEMM_SMEM_BYTES ((GEMM_SA_WORDS + GEMM_SB_WORDS) * 4)

__global__ __launch_bounds__(256) void sgemm_qkv() {
    extern __shared__ uint32_t smg[];
    uint32_t* sA = smg;
    uint32_t* sB = smg + GEMM_SA_WORDS;

    int tid = threadIdx.x;
    int warp = tid >> 5, lane = tid & 31;
    int g = lane >> 2, qd = lane & 3;
    int wm = warp & 1, wn = warp >> 1;

    int cn = blockIdx.x * 128;
    int rm = blockIdx.y * 128;

    const float* W;
    int ldb, mode, colOff;
    if (cn < 2048)      { W = g_wq; ldb = NH_ * H_; colOff = cn;        mode = 0; }
    else if (cn < 3072) { W = g_wk; ldb = KH_ * H_; colOff = cn - 2048; mode = 1; }
    else                { W = g_wv; ldb = KH_ * H_; colOff = cn - 3072; mode = 2; }
    int head = colOff >> 7;

    uint32_t sA_base = (uint32_t)__cvta_generic_to_shared(sA);
    uint32_t sB_base = (uint32_t)__cvta_generic_to_shared(sB);

    int arA = tid >> 3, acA = (tid & 7) << 2;
    int arB = tid >> 5, acB = (tid & 31) << 2;

    float c[4][4][4];
#pragma unroll
    for (int mt = 0; mt < 4; mt++)
#pragma unroll
        for (int nt = 0; nt < 4; nt++)
#pragma unroll
            for (int i = 0; i < 4; i++) c[mt][nt][i] = 0.0f;

    auto load_stage = [&](int kk, int st) {
#pragma unroll
        for (int i = 0; i < 4; i++) {
            int r = arA + i * 32;
            cpa16(sA_base + (st * 128 * 36 + r * 36 + acA) * 4,
                  g_x + (size_t)(rm + r) * D_ + kk + acA);
        }
#pragma unroll
        for (int i = 0; i < 4; i++) {
            int r = arB + i * 8;
            cpa16(sB_base + (st * 32 * 136 + r * 136 + acB) * 4,
                  W + (size_t)(kk + r) * ldb + colOff + acB);
        }
        cpa_commit();
    };

    load_stage(0, 0);

    const int KT = D_ / 32;
    for (int kt = 0; kt < KT; kt++) {
        if (kt + 1 < KT) load_stage((kt + 1) * 32, (kt + 1) & 1);
        if (kt + 1 < KT) cpa_wait1(); else cpa_wait0();
        __syncthreads();

        const uint32_t* A  = sA + (kt & 1) * 128 * 36;
        const uint32_t* Bm = sB + (kt & 1) * 32 * 136;
#pragma unroll
        for (int ks = 0; ks < 4; ks++) {
            int k0 = ks * 8;
            uint32_t a[4][4];
#pragma unroll
            for (int mt = 0; mt < 4; mt++) {
                int ar = wm * 64 + mt * 16 + g;
                a[mt][0] = A[ar * 36 + k0 + qd];
                a[mt][1] = A[(ar + 8) * 36 + k0 + qd];
                a[mt][2] = A[ar * 36 + k0 + 4 + qd];
                a[mt][3] = A[(ar + 8) * 36 + k0 + 4 + qd];
            }
            uint32_t b[4][2];
#pragma unroll
            for (int nt = 0; nt < 4; nt++) {
                int bc = wn * 32 + nt * 8 + g;
                b[nt][0] = Bm[(k0 + qd) * 136 + bc];
                b[nt][1] = Bm[(k0 + 4 + qd) * 136 + bc];
            }
#pragma unroll
            for (int mt = 0; mt < 4; mt++)
#pragma unroll
                for (int nt = 0; nt < 4; nt++)
                    mma_tf32(c[mt][nt], a[mt][0], a[mt][1], a[mt][2], a[mt][3],
                             b[nt][0], b[nt][1]);
        }
        __syncthreads();
    }

    float* base = (mode == 0) ? g_q : (mode == 1 ? g_k : g_v);
    int heads = (mode == 0) ? NH_ : KH_;
    bool roundV = (mode == 2);
#pragma unroll
    for (int mt = 0; mt < 4; mt++) {
#pragma unroll
        for (int nt = 0; nt < 4; nt++) {
            int col = wn * 32 + nt * 8 + qd * 2;
            int rr0 = rm + wm * 64 + mt * 16 + g;
            int rr1 = rr0 + 8;
            int b0 = rr0 >> 11, t0 = rr0 & 2047;
            int b1 = rr1 >> 11, t1 = rr1 & 2047;
            float* d0 = base + ((size_t)(b0 * heads + head) * T_ + t0) * H_ + col;
            float* d1 = base + ((size_t)(b1 * heads + head) * T_ + t1) * H_ + col;
            float v0 = c[mt][nt][0], v1 = c[mt][nt][1];
            float v2 = c[mt][nt][2], v3 = c[mt][nt][3];
            if (roundV) {
                v0 = __uint_as_float(f2tf32(v0));
                v1 = __uint_as_float(f2tf32(v1));
                v2 = __uint_as_float(f2tf32(v2));
                v3 = __uint_as_float(f2tf32(v3));
            }
            *(float2*)d0 = make_float2(v0, v1);
            *(float2*)d1 = make_float2(v2, v3);
        }
    }
}

// ---------------------------------------------------------------------------
// RMSNorm + RoPE for q and k, stores tf32-rounded.
// ---------------------------------------------------------------------------
__global__ __launch_bounds__(128) void norm_rope_kernel(const float* __restrict__ qscale,
                                                        const float* __restrict__ kscale) {
    int row = blockIdx.x;
    const int QROWS = B_ * NH_ * T_;
    float* data;
    const float* scale;
    int b, t;
    if (row < QROWS) {
        data = g_q + (size_t)row * H_;
        scale = qscale;
        b = row / (NH_ * T_);
        t = row % T_;
    } else {
        int r = row - QROWS;
        data = g_k + (size_t)r * H_;
        scale = kscale;
        b = r / (KH_ * T_);
        t = r % T_;
    }
    int i = threadIdx.x;

    float v = data[i];
    float ss = v * v;
#pragma unroll
    for (int o = 16; o; o >>= 1) ss += __shfl_xor_sync(0xffffffffu, ss, o);
    __shared__ float ws[4];
    if ((i & 31) == 0) ws[i >> 5] = ss;
    __syncthreads();
    float tot = ws[0] + ws[1] + ws[2] + ws[3];
    float rinv = rsqrtf(tot * (1.0f / 128.0f) + 1e-6f);

    __shared__ float sx[128];
    sx[i] = scale[i] * v * rinv;
    __syncthreads();

    if (i < 64) {
        int pos = g_pos[b * T_ + t];
        float inv = exp2f(-((float)i * (1.0f / 64.0f)) * 19.931568569324174f);
        float ang = (float)pos * inv;
        float sn, cs;
        sincosf(ang, &sn, &cs);
        float x1 = sx[i], x2 = sx[i + 64];
        data[i]      = __uint_as_float(f2tf32(x1 * cs - x2 * sn));
        data[i + 64] = __uint_as_float(f2tf32(x2 * cs + x1 * sn));
    }
}

// ---------------------------------------------------------------------------
// Flash attention, tf32 mma. Q tile 128 rows, KV tile 64 cols, 512 THREADS
// (16 warps: 8 row-groups x 2 col-halves). Single-buffered cp.async KV,
// LPT ordering. smem = 174,080 B.
// ---------------------------------------------------------------------------
#define SQ_OFF   0                          // 128*132
#define SK_OFF   (SQ_OFF + 128 * 132)       // 64*132
#define SV_OFF   (SK_OFF + 64 * 132)        // 64*136
#define SS_OFF   (SV_OFF + 64 * 136)        // 128*68
#define SM_OFF   (SS_OFF + 128 * 68)
#define SL_OFF   (SM_OFF + 128)
#define SF_OFF   (SL_OFF + 128)
#define PT_OFF   (SF_OFF + 128)
#define ST_OFF   (PT_OFF + 128)
#define PS_OFF   (ST_OFF + 128)             // 64
#define SSG_OFF  (PS_OFF + 64)              // 64
#define ATTN_SMEM_WORDS (SSG_OFF + 64)

__global__ __launch_bounds__(512, 1) void attn_kernel(const int* __restrict__ seg) {
    extern __shared__ uint32_t smu[];
    uint32_t* sQ  = smu + SQ_OFF;
    uint32_t* sK  = smu + SK_OFF;
    uint32_t* sV  = smu + SV_OFF;
    float*    sS  = (float*)(smu + SS_OFF);
    uint32_t* sSu = smu + SS_OFF;
    float*    sM  = (float*)(smu + SM_OFF);
    float*    sL  = (float*)(smu + SL_OFF);
    float*    sF  = (float*)(smu + SF_OFF);
    int*      sPT = (int*)(smu + PT_OFF);
    int*      sST = (int*)(smu + ST_OFF);
    int*      sPS = (int*)(smu + PS_OFF);
    int*      sSG = (int*)(smu + SSG_OFF);

    uint32_t smem_base = (uint32_t)__cvta_generic_to_shared(smu);

    int tid = threadIdx.x;
    int warp = tid >> 5, lane = tid & 31;
    int g = lane >> 2, qd = lane & 3;
    int wm = warp >> 1, wn = warp & 1;   // wm 0..7 (16 rows each), wn 0..1

    int bid = blockIdx.x;
    int itile = 15 - (bid & 15);         // LPT: longest CTAs first
    int n  = (bid >> 4) & 15;
    int b  = bid >> 8;
    int kvh = n >> 1;
    int t0 = itile * 128;

    const float* Qb = g_q + (size_t)(b * NH_ + n)   * T_ * H_;
    const float* Kb = g_k + (size_t)(b * KH_ + kvh) * T_ * H_;
    const float* Vb = g_v + (size_t)(b * KH_ + kvh) * T_ * H_;
    const int* posb = g_pos + b * T_;
    const int* segb = seg + b * T_;

    int lr = tid >> 5;          // 0..15 row group for loads
    int lc = (tid & 31) << 2;   // 0..124 col (x4)

    // Load Q tile (128 rows) via cp.async
#pragma unroll
    for (int i = 0; i < 8; i++) {
        int r = lr + i * 16;
        cpa16(smem_base + (SQ_OFF + r * 132 + lc) * 4,
              Qb + (size_t)(t0 + r) * H_ + lc);
    }
    cpa_commit();

    if (tid < 128) {
        sM[tid] = -3.0e38f; sL[tid] = 0.0f;
        sPT[tid] = posb[t0 + tid];
        sST[tid] = segb[t0 + tid];
    }

    int r0 = wm * 16 + g, r1 = r0 + 8;
    int row4 = tid >> 2, part = tid & 3;   // softmax: 4 threads/row, 16 cols each

    float cO[8][4];
#pragma unroll
    for (int i = 0; i < 8; i++)
#pragma unroll
        for (int j = 0; j < 4; j++) cO[i][j] = 0.0f;

    int numjt = 2 * itile + 2;
    for (int jt = 0; jt < numjt; jt++) {
        int s0 = jt * 64;

        // load K, V tiles via cp.async (single buffer)
#pragma unroll
        for (int i = 0; i < 4; i++) {
            int r = lr + i * 16;
            cpa16(smem_base + (SK_OFF + r * 132 + lc) * 4,
                  Kb + (size_t)(s0 + r) * H_ + lc);
            cpa16(smem_base + (SV_OFF + r * 136 + lc) * 4,
                  Vb + (size_t)(s0 + r) * H_ + lc);
        }
        cpa_commit();
        if (tid < 64) {
            sPS[tid] = posb[s0 + tid];
            sSG[tid] = segb[s0 + tid];
        }
        cpa_wait0();
        __syncthreads();

        // ---- S = Q K^T  (128 x 64); warp computes 16 rows x 32 cols ----
        float cS[4][4];
#pragma unroll
        for (int nt = 0; nt < 4; nt++)
#pragma unroll
            for (int j = 0; j < 4; j++) cS[nt][j] = 0.0f;

#pragma unroll
        for (int k0 = 0; k0 < 128; k0 += 8) {
            uint32_t a0 = sQ[r0 * 132 + k0 + qd];
            uint32_t a1 = sQ[r1 * 132 + k0 + qd];
            uint32_t a2 = sQ[r0 * 132 + k0 + 4 + qd];
            uint32_t a3 = sQ[r1 * 132 + k0 + 4 + qd];
#pragma unroll
            for (int nt = 0; nt < 4; nt++) {
                int bc = wn * 32 + nt * 8 + g;
                uint32_t b0 = sK[bc * 132 + k0 + qd];
                uint32_t b1 = sK[bc * 132 + k0 + 4 + qd];
                mma_tf32(cS[nt], a0, a1, a2, a3, b0, b1);
            }
        }

        // mask + scale -> sS
        {
            int pt0 = sPT[r0], st0 = sST[r0];
            int pt1 = sPT[r1], st1 = sST[r1];
#pragma unroll
            for (int nt = 0; nt < 4; nt++) {
                int col = wn * 32 + nt * 8 + qd * 2;
                int ps0 = sPS[col], ss0 = sSG[col];
                int ps1 = sPS[col + 1], ss1 = sSG[col + 1];
                sS[r0 * 68 + col]     = (ps0 <= pt0 && ss0 == st0) ? cS[nt][0] * SCALE_ : KMASK_;
                sS[r0 * 68 + col + 1] = (ps1 <= pt0 && ss1 == st0) ? cS[nt][1] * SCALE_ : KMASK_;
                sS[r1 * 68 + col]     = (ps0 <= pt1 && ss0 == st1) ? cS[nt][2] * SCALE_ : KMASK_;
                sS[r1 * 68 + col + 1] = (ps1 <= pt1 && ss1 == st1) ? cS[nt][3] * SCALE_ : KMASK_;
            }
        }
        __syncthreads();

        // ---- online softmax (4 threads per row, 16 cols each) ----
        {
            float m_old = sM[row4];
            float vals[16];
            float mx = KMASK_;
#pragma unroll
            for (int c = 0; c < 16; c++) {
                vals[c] = sS[row4 * 68 + part * 16 + c];
                mx = fmaxf(mx, vals[c]);
            }
            mx = fmaxf(mx, __shfl_xor_sync(0xffffffffu, mx, 1));
            mx = fmaxf(mx, __shfl_xor_sync(0xffffffffu, mx, 2));
            float m_new = fmaxf(m_old, mx);
            float sum = 0.0f;
#pragma unroll
            for (int c = 0; c < 16; c++) {
                float pv = __expf(vals[c] - m_new);
                sum += pv;
                sSu[row4 * 68 + part * 16 + c] = f2tf32(pv);
            }
            sum += __shfl_xor_sync(0xffffffffu, sum, 1);
            sum += __shfl_xor_sync(0xffffffffu, sum, 2);
            if (part == 0) {
                float f = __expf(m_old - m_new);
                sL[row4] = sL[row4] * f + sum;
                sM[row4] = m_new;
                sF[row4] = f;
            }
        }
        __syncthreads();

        // ---- O = O*f + P V ; warp covers rows r0/r1 x 64 cols (wn half) ----
        float f0 = sF[r0], f1 = sF[r1];
#pragma unroll
        for (int nt = 0; nt < 8; nt++) {
            cO[nt][0] *= f0; cO[nt][1] *= f0;
            cO[nt][2] *= f1; cO[nt][3] *= f1;
        }
#pragma unroll
        for (int k0 = 0; k0 < 64; k0 += 8) {
            uint32_t a0 = sSu[r0 * 68 + k0 + qd];
            uint32_t a1 = sSu[r1 * 68 + k0 + qd];
            uint32_t a2 = sSu[r0 * 68 + k0 + 4 + qd];
            uint32_t a3 = sSu[r1 * 68 + k0 + 4 + qd];
#pragma unroll
            for (int nt = 0; nt < 8; nt++) {
                int vc = wn * 64 + nt * 8 + g;
                uint32_t b0 = sV[(k0 + qd) * 136 + vc];
                uint32_t b1 = sV[(k0 + 4 + qd) * 136 + vc];
                mma_tf32(cO[nt], a0, a1, a2, a3, b0, b1);
            }
        }
        __syncthreads();
    }

    // normalize + store (tf32-rounded for the out-projection)
    float inv0 = 1.0f / sL[r0];
    float inv1 = 1.0f / sL[r1];
#pragma unroll
    for (int nt = 0; nt < 8; nt++) {
        int col = wn * 64 + nt * 8 + qd * 2;
        float* d0 = g_o + ((size_t)(b * T_ + t0 + r0) * NH_ + n) * H_ + col;
        float* d1 = g_o + ((size_t)(b * T_ + t0 + r1) * NH_ + n) * H_ + col;
        *(float2*)d0 = make_float2(__uint_as_float(f2tf32(cO[nt][0] * inv0)),
                                   __uint_as_float(f2tf32(cO[nt][1] * inv0)));
        *(float2*)d1 = make_float2(__uint_as_float(f2tf32(cO[nt][2] * inv1)),
                                   __uint_as_float(f2tf32(cO[nt][3] * inv1)));
    }
}

// ---------------------------------------------------------------------------
// Output projection (tf32 mma, cp.async 2-stage).
// ---------------------------------------------------------------------------
__global__ __launch_bounds__(256) void sgemm_out(float* __restrict__ out) {
    extern __shared__ uint32_t smg[];
    uint32_t* sA = smg;
    uint32_t* sB = smg + GEMM_SA_WORDS;

    int tid = threadIdx.x;
    int warp = tid >> 5, lane = tid & 31;
    int g = lane >> 2, qd = lane & 3;
    int wm = warp & 1, wn = warp >> 1;

    int cn = blockIdx.x * 128;
    int rm = blockIdx.y * 128;

    uint32_t sA_base = (uint32_t)__cvta_generic_to_shared(sA);
    uint32_t sB_base = (uint32_t)__cvta_generic_to_shared(sB);

    int arA = tid >> 3, acA = (tid & 7) << 2;
    int arB = tid >> 5, acB = (tid & 31) << 2;

    float c[4][4][4];
#pragma unroll
    for (int mt = 0; mt < 4; mt++)
#pragma unroll
        for (int nt = 0; nt < 4; nt++)
#pragma unroll
            for (int i = 0; i < 4; i++) c[mt][nt][i] = 0.0f;

    auto load_stage = [&](int kk, int st) {
#pragma unroll
        for (int i = 0; i < 4; i++) {
            int r = arA + i * 32;
            cpa16(sA_base + (st * 128 * 36 + r * 36 + acA) * 4,
                  g_o + (size_t)(rm + r) * (NH_ * H_) + kk + acA);
        }
#pragma unroll
        for (int i = 0; i < 4; i++) {
            int r = arB + i * 8;
            cpa16(sB_base + (st * 32 * 136 + r * 136 + acB) * 4,
                  g_wo + (size_t)(kk + r) * D_ + cn + acB);
        }
        cpa_commit();
    };

    load_stage(0, 0);

    const int KT = (NH_ * H_) / 32;
    for (int kt = 0; kt < KT; kt++) {
        if (kt + 1 < KT) load_stage((kt + 1) * 32, (kt + 1) & 1);
        if (kt + 1 < KT) cpa_wait1(); else cpa_wait0();
        __syncthreads();

        const uint32_t* A  = sA + (kt & 1) * 128 * 36;
        const uint32_t* Bm = sB + (kt & 1) * 32 * 136;
#pragma unroll
        for (int ks = 0; ks < 4; ks++) {
            int k0 = ks * 8;
            uint32_t a[4][4];
#pragma unroll
            for (int mt = 0; mt < 4; mt++) {
                int ar = wm * 64 + mt * 16 + g;
                a[mt][0] = A[ar * 36 + k0 + qd];
                a[mt][1] = A[(ar + 8) * 36 + k0 + qd];
                a[mt][2] = A[ar * 36 + k0 + 4 + qd];
                a[mt][3] = A[(ar + 8) * 36 + k0 + 4 + qd];
            }
            uint32_t b[4][2];
#pragma unroll
            for (int nt = 0; nt < 4; nt++) {
                int bc = wn * 32 + nt * 8 + g;
                b[nt][0] = Bm[(k0 + qd) * 136 + bc];
                b[nt][1] = Bm[(k0 + 4 + qd) * 136 + bc];
            }
#pragma unroll
            for (int mt = 0; mt < 4; mt++)
#pragma unroll
                for (int nt = 0; nt < 4; nt++)
                    mma_tf32(c[mt][nt], a[mt][0], a[mt][1], a[mt][2], a[mt][3],
                             b[nt][0], b[nt][1]);
        }
        __syncthreads();
    }

#pragma unroll
    for (int mt = 0; mt < 4; mt++) {
#pragma unroll
        for (int nt = 0; nt < 4; nt++) {
            int col = cn + wn * 32 + nt * 8 + qd * 2;
            int rr0 = rm + wm * 64 + mt * 16 + g;
            int rr1 = rr0 + 8;
            *(float2*)(out + (size_t)rr0 * D_ + col) = make_float2(c[mt][nt][0], c[mt][nt][1]);
            *(float2*)(out + (size_t)rr1 * D_ + col) = make_float2(c[mt][nt][2], c[mt][nt][3]);
        }
    }
}

// ---------------------------------------------------------------------------
extern "C" void kernel_launch(void* const* d_in, const int* in_sizes, int n_in,
                              void* d_out, int out_size) {
    const float* x  = (const float*)d_in[0];
    const int*   sg = (const int*)d_in[1];
    const float* wq = (const float*)d_in[2];
    const float* wk = (const float*)d_in[3];
    const float* wv = (const float*)d_in[4];
    const float* wo = (const float*)d_in[5];
    const float* qs = (const float*)d_in[6];
    const float* ks = (const float*)d_in[7];
    float* out = (float*)d_out;

    cudaFuncSetAttribute(sgemm_qkv, cudaFuncAttributeMaxDynamicSharedMemorySize,
                         GEMM_SMEM_BYTES);
    cudaFuncSetAttribute(sgemm_out, cudaFuncAttributeMaxDynamicSharedMemorySize,
                         GEMM_SMEM_BYTES);
    cudaFuncSetAttribute(attn_kernel, cudaFuncAttributeMaxDynamicSharedMemorySize,
                         ATTN_SMEM_WORDS * 4);

    pos_kernel<<<B_, 256>>>(sg);                                    // 1
    round_x_kernel<<<512, 256>>>(x);                                // 2
    round_w_kernel<<<512, 256>>>(wq, wk, wv, wo);                   // 3
    sgemm_qkv<<<dim3(32, 32), 256, GEMM_SMEM_BYTES>>>();            // 4
    norm_rope_kernel<<<B_ * (NH_ + KH_) * T_, 128>>>(qs, ks);       // 5
    attn_kernel<<<B_ * NH_ * 16, 512, ATTN_SMEM_WORDS * 4>>>(sg);   // 6
    sgemm_out<<<dim3(8, 32), 256, GEMM_SMEM_BYTES>>>(out);          // 7
}

// round 13
// speedup vs baseline: 1.1145x; 1.1145x over previous
#include <cuda_runtime.h>
#include <cuda_bf16.h>
#include <cstdint>

#define B_ 2
#define T_ 2048
#define D_ 1024
#define NH_ 16
#define KH_ 8
#define H_ 128

static constexpr float SCALE_ = 0.08838834764831845f;   // 128^-0.5
static constexpr float KMASK_ = -3.4028234663852886e38f;

// Scratch (device globals; no runtime allocation allowed)
__device__ float g_q[(size_t)B_ * NH_ * T_ * H_];   // [B][N][T][H] (tf32-rounded)
__device__ float g_k[(size_t)B_ * KH_ * T_ * H_];   // [B][K][S][H] (tf32-rounded)
__device__ float g_v[(size_t)B_ * KH_ * T_ * H_];   // [B][K][S][H] (tf32-rounded)
__device__ float g_o[(size_t)B_ * T_ * NH_ * H_];   // [B][T][N][H] (tf32-rounded)
__device__ int   g_pos[B_ * T_];
// tf32-rounded copies of inputs
__device__ float g_x [(size_t)B_ * T_ * D_];
__device__ float g_wq[(size_t)D_ * NH_ * H_];
__device__ float g_wk[(size_t)D_ * KH_ * H_];
__device__ float g_wv[(size_t)D_ * KH_ * H_];
__device__ float g_wo[(size_t)NH_ * H_ * D_];

// ---------------------------------------------------------------------------
__device__ __forceinline__ uint32_t f2tf32(float x) {
    uint32_t r;
    asm("cvt.rna.tf32.f32 %0, %1;" : "=r"(r) : "f"(x));
    return r;
}

__device__ __forceinline__ void mma_tf32(float* c,
                                         uint32_t a0, uint32_t a1, uint32_t a2, uint32_t a3,
                                         uint32_t b0, uint32_t b1) {
    asm volatile(
        "mma.sync.aligned.m16n8k8.row.col.f32.tf32.tf32.f32 "
        "{%0,%1,%2,%3}, {%4,%5,%6,%7}, {%8,%9}, {%0,%1,%2,%3};\n"
        : "+f"(c[0]), "+f"(c[1]), "+f"(c[2]), "+f"(c[3])
        : "r"(a0), "r"(a1), "r"(a2), "r"(a3), "r"(b0), "r"(b1));
}

__device__ __forceinline__ void cpa16(uint32_t saddr, const void* gptr) {
    asm volatile("cp.async.ca.shared.global [%0], [%1], 16;\n"
                 :: "r"(saddr), "l"(gptr));
}
__device__ __forceinline__ void cpa_commit() {
    asm volatile("cp.async.commit_group;\n" ::: "memory");
}
__device__ __forceinline__ void cpa_wait0() {
    asm volatile("cp.async.wait_group 0;\n" ::: "memory");
}
__device__ __forceinline__ void cpa_wait1() {
    asm volatile("cp.async.wait_group 1;\n" ::: "memory");
}

// ---------------------------------------------------------------------------
// Positions from segment ids.
// ---------------------------------------------------------------------------
__global__ __launch_bounds__(256) void pos_kernel(const int* __restrict__ seg) {
    int b = blockIdx.x;
    int tid = threadIdx.x;
    __shared__ int sred[256];

    int mv = -2147483647 - 1;
    for (int t = tid; t < T_; t += 256) mv = max(mv, seg[b * T_ + t]);
    sred[tid] = mv;
    __syncthreads();
    for (int st = 128; st > 0; st >>= 1) {
        if (tid < st) sred[tid] = max(sred[tid], sred[tid + st]);
        __syncthreads();
    }
    int maxv = sred[0];
    __syncthreads();

    int mi = 0x7fffffff;
    for (int t = tid; t < T_; t += 256)
        if (seg[b * T_ + t] == maxv) mi = min(mi, t);
    sred[tid] = mi;
    __syncthreads();
    for (int st = 128; st > 0; st >>= 1) {
        if (tid < st) sred[tid] = min(sred[tid], sred[tid + st]);
        __syncthreads();
    }
    int off = sred[0];

    for (int t = tid; t < T_; t += 256) {
        int s = seg[b * T_ + t];
        g_pos[b * T_ + t] = (s != 0) ? (t - off) : (1 << 30);
    }
}

// ---------------------------------------------------------------------------
// Round x to tf32 into g_x.
// ---------------------------------------------------------------------------
__global__ __launch_bounds__(256) void round_x_kernel(const float* __restrict__ src) {
    const int n4 = (B_ * T_ * D_) / 4;
    int i = blockIdx.x * 256 + threadIdx.x;
    int stride = gridDim.x * 256;
    for (; i < n4; i += stride) {
        float4 v = *(const float4*)(src + (size_t)i * 4);
        v.x = __uint_as_float(f2tf32(v.x));
        v.y = __uint_as_float(f2tf32(v.y));
        v.z = __uint_as_float(f2tf32(v.z));
        v.w = __uint_as_float(f2tf32(v.w));
        *(float4*)(g_x + (size_t)i * 4) = v;
    }
}

// ---------------------------------------------------------------------------
// Round all 4 weight tensors to tf32 (flat index over concat).
// ---------------------------------------------------------------------------
__global__ __launch_bounds__(256) void round_w_kernel(const float* __restrict__ wq,
                                                      const float* __restrict__ wk,
                                                      const float* __restrict__ wv,
                                                      const float* __restrict__ wo) {
    const int N4 = 1572864;
    int i = blockIdx.x * 256 + threadIdx.x;
    int stride = gridDim.x * 256;
    for (; i < N4; i += stride) {
        const float* src;
        float* dst;
        int j;
        if (i < 524288)       { src = wq; dst = g_wq; j = i; }
        else if (i < 786432)  { src = wk; dst = g_wk; j = i - 524288; }
        else if (i < 1048576) { src = wv; dst = g_wv; j = i - 786432; }
        else                  { src = wo; dst = g_wo; j = i - 1048576; }
        float4 v = *(const float4*)(src + (size_t)j * 4);
        v.x = __uint_as_float(f2tf32(v.x));
        v.y = __uint_as_float(f2tf32(v.y));
        v.z = __uint_as_float(f2tf32(v.z));
        v.w = __uint_as_float(f2tf32(v.w));
        *(float4*)(dst + (size_t)j * 4) = v;
    }
}

// ---------------------------------------------------------------------------
// QKV projection GEMM (tf32 mma, cp.async 2-stage, dyn smem 71,680B).
// ---------------------------------------------------------------------------
#define GEMM_SA_WORDS (2 * 128 * 36)
#define GEMM_SB_WORDS (2 * 32 * 136)
#define GEMM_SMEM_BYTES ((GEMM_SA_WORDS + GEMM_SB_WORDS) * 4)

__global__ __launch_bounds__(256) void sgemm_qkv() {
    extern __shared__ uint32_t smg[];
    uint32_t* sA = smg;
    uint32_t* sB = smg + GEMM_SA_WORDS;

    int tid = threadIdx.x;
    int warp = tid >> 5, lane = tid & 31;
    int g = lane >> 2, qd = lane & 3;
    int wm = warp & 1, wn = warp >> 1;

    int cn = blockIdx.x * 128;
    int rm = blockIdx.y * 128;

    const float* W;
    int ldb, mode, colOff;
    if (cn < 2048)      { W = g_wq; ldb = NH_ * H_; colOff = cn;        mode = 0; }
    else if (cn < 3072) { W = g_wk; ldb = KH_ * H_; colOff = cn - 2048; mode = 1; }
    else                { W = g_wv; ldb = KH_ * H_; colOff = cn - 3072; mode = 2; }
    int head = colOff >> 7;

    uint32_t sA_base = (uint32_t)__cvta_generic_to_shared(sA);
    uint32_t sB_base = (uint32_t)__cvta_generic_to_shared(sB);

    int arA = tid >> 3, acA = (tid & 7) << 2;
    int arB = tid >> 5, acB = (tid & 31) << 2;

    float c[4][4][4];
#pragma unroll
    for (int mt = 0; mt < 4; mt++)
#pragma unroll
        for (int nt = 0; nt < 4; nt++)
#pragma unroll
            for (int i = 0; i < 4; i++) c[mt][nt][i] = 0.0f;

    auto load_stage = [&](int kk, int st) {
#pragma unroll
        for (int i = 0; i < 4; i++) {
            int r = arA + i * 32;
            cpa16(sA_base + (st * 128 * 36 + r * 36 + acA) * 4,
                  g_x + (size_t)(rm + r) * D_ + kk + acA);
        }
#pragma unroll
        for (int i = 0; i < 4; i++) {
            int r = arB + i * 8;
            cpa16(sB_base + (st * 32 * 136 + r * 136 + acB) * 4,
                  W + (size_t)(kk + r) * ldb + colOff + acB);
        }
        cpa_commit();
    };

    load_stage(0, 0);

    const int KT = D_ / 32;
    for (int kt = 0; kt < KT; kt++) {
        if (kt + 1 < KT) load_stage((kt + 1) * 32, (kt + 1) & 1);
        if (kt + 1 < KT) cpa_wait1(); else cpa_wait0();
        __syncthreads();

        const uint32_t* A  = sA + (kt & 1) * 128 * 36;
        const uint32_t* Bm = sB + (kt & 1) * 32 * 136;
#pragma unroll
        for (int ks = 0; ks < 4; ks++) {
            int k0 = ks * 8;
            uint32_t a[4][4];
#pragma unroll
            for (int mt = 0; mt < 4; mt++) {
                int ar = wm * 64 + mt * 16 + g;
                a[mt][0] = A[ar * 36 + k0 + qd];
                a[mt][1] = A[(ar + 8) * 36 + k0 + qd];
                a[mt][2] = A[ar * 36 + k0 + 4 + qd];
                a[mt][3] = A[(ar + 8) * 36 + k0 + 4 + qd];
            }
            uint32_t b[4][2];
#pragma unroll
            for (int nt = 0; nt < 4; nt++) {
                int bc = wn * 32 + nt * 8 + g;
                b[nt][0] = Bm[(k0 + qd) * 136 + bc];
                b[nt][1] = Bm[(k0 + 4 + qd) * 136 + bc];
            }
#pragma unroll
            for (int mt = 0; mt < 4; mt++)
#pragma unroll
                for (int nt = 0; nt < 4; nt++)
                    mma_tf32(c[mt][nt], a[mt][0], a[mt][1], a[mt][2], a[mt][3],
                             b[nt][0], b[nt][1]);
        }
        __syncthreads();
    }

    float* base = (mode == 0) ? g_q : (mode == 1 ? g_k : g_v);
    int heads = (mode == 0) ? NH_ : KH_;
    bool roundV = (mode == 2);
#pragma unroll
    for (int mt = 0; mt < 4; mt++) {
#pragma unroll
        for (int nt = 0; nt < 4; nt++) {
            int col = wn * 32 + nt * 8 + qd * 2;
            int rr0 = rm + wm * 64 + mt * 16 + g;
            int rr1 = rr0 + 8;
            int b0 = rr0 >> 11, t0 = rr0 & 2047;
            int b1 = rr1 >> 11, t1 = rr1 & 2047;
            float* d0 = base + ((size_t)(b0 * heads + head) * T_ + t0) * H_ + col;
            float* d1 = base + ((size_t)(b1 * heads + head) * T_ + t1) * H_ + col;
            float v0 = c[mt][nt][0], v1 = c[mt][nt][1];
            float v2 = c[mt][nt][2], v3 = c[mt][nt][3];
            if (roundV) {
                v0 = __uint_as_float(f2tf32(v0));
                v1 = __uint_as_float(f2tf32(v1));
                v2 = __uint_as_float(f2tf32(v2));
                v3 = __uint_as_float(f2tf32(v3));
            }
            *(float2*)d0 = make_float2(v0, v1);
            *(float2*)d1 = make_float2(v2, v3);
        }
    }
}

// ---------------------------------------------------------------------------
// RMSNorm + RoPE, warp-per-row (8 rows per 256-thr block), no block barriers.
// Same per-element math as before; only the RMS sum order differs.
// ---------------------------------------------------------------------------
__global__ __launch_bounds__(256) void norm_rope_kernel(const float* __restrict__ qscale,
                                                        const float* __restrict__ kscale) {
    int wid = threadIdx.x >> 5, lane = threadIdx.x & 31;
    int row = blockIdx.x * 8 + wid;
    const int QROWS = B_ * NH_ * T_;
    float* data;
    const float* scale;
    int b, t;
    if (row < QROWS) {
        data = g_q + (size_t)row * H_;
        scale = qscale;
        b = row / (NH_ * T_);
        t = row % T_;
    } else {
        int r = row - QROWS;
        data = g_k + (size_t)r * H_;
        scale = kscale;
        b = r / (KH_ * T_);
        t = r % T_;
    }

    float4 v = *(const float4*)(data + lane * 4);
    float ss = v.x * v.x + v.y * v.y + v.z * v.z + v.w * v.w;
#pragma unroll
    for (int o = 16; o; o >>= 1) ss += __shfl_xor_sync(0xffffffffu, ss, o);
    float rinv = rsqrtf(ss * (1.0f / 128.0f) + 1e-6f);

    float4 sc = *(const float4*)(scale + lane * 4);
    float x[4] = { sc.x * v.x * rinv, sc.y * v.y * rinv,
                   sc.z * v.z * rinv, sc.w * v.w * rinv };

    int pos = g_pos[b * T_ + t];
    int j = lane & 15;                       // rope frequency row 0..15 (x4)
    bool lowHalf = (lane < 16);
    float out[4];
#pragma unroll
    for (int k = 0; k < 4; k++) {
        int idx = j * 4 + k;                 // 0..63
        float inv = exp2f(-((float)idx * (1.0f / 64.0f)) * 19.931568569324174f);
        float ang = (float)pos * inv;
        float sn, cs;
        sincosf(ang, &sn, &cs);
        float xo = __shfl_xor_sync(0xffffffffu, x[k], 16);
        // lowHalf: this = x1, xo = x2 -> x1*c - x2*s
        // high:    this = x2, xo = x1 -> x2*c + x1*s
        float r = lowHalf ? (x[k] * cs - xo * sn) : (x[k] * cs + xo * sn);
        out[k] = __uint_as_float(f2tf32(r));
    }
    *(float4*)(data + lane * 4) = make_float4(out[0], out[1], out[2], out[3]);
}

// ---------------------------------------------------------------------------
// Flash attention (EXACT R10): Q tile 128 rows, KV tile 64 cols, 256 threads,
// single-buffered cp.async KV, LPT ordering. smem = 174,080 B.
// ---------------------------------------------------------------------------
#define SQ_OFF   0                          // 128*132
#define SK_OFF   (SQ_OFF + 128 * 132)       // 64*132
#define SV_OFF   (SK_OFF + 64 * 132)        // 64*136
#define SS_OFF   (SV_OFF + 64 * 136)        // 128*68
#define SM_OFF   (SS_OFF + 128 * 68)
#define SL_OFF   (SM_OFF + 128)
#define SF_OFF   (SL_OFF + 128)
#define PT_OFF   (SF_OFF + 128)
#define ST_OFF   (PT_OFF + 128)
#define PS_OFF   (ST_OFF + 128)             // 64
#define SSG_OFF  (PS_OFF + 64)              // 64
#define ATTN_SMEM_WORDS (SSG_OFF + 64)

__global__ __launch_bounds__(256, 1) void attn_kernel(const int* __restrict__ seg) {
    extern __shared__ uint32_t smu[];
    uint32_t* sQ  = smu + SQ_OFF;
    uint32_t* sK  = smu + SK_OFF;
    uint32_t* sV  = smu + SV_OFF;
    float*    sS  = (float*)(smu + SS_OFF);
    uint32_t* sSu = smu + SS_OFF;
    float*    sM  = (float*)(smu + SM_OFF);
    float*    sL  = (float*)(smu + SL_OFF);
    float*    sF  = (float*)(smu + SF_OFF);
    int*      sPT = (int*)(smu + PT_OFF);
    int*      sST = (int*)(smu + ST_OFF);
    int*      sPS = (int*)(smu + PS_OFF);
    int*      sSG = (int*)(smu + SSG_OFF);

    uint32_t smem_base = (uint32_t)__cvta_generic_to_shared(smu);

    int tid = threadIdx.x;
    int warp = tid >> 5, lane = tid & 31;
    int g = lane >> 2, qd = lane & 3;
    int wm = warp >> 1, wn = warp & 1;   // wm 0..3 (32 rows each), wn 0..1

    int bid = blockIdx.x;
    int itile = 15 - (bid & 15);         // LPT: longest CTAs first
    int n  = (bid >> 4) & 15;
    int b  = bid >> 8;
    int kvh = n >> 1;
    int t0 = itile * 128;

    const float* Qb = g_q + (size_t)(b * NH_ + n)   * T_ * H_;
    const float* Kb = g_k + (size_t)(b * KH_ + kvh) * T_ * H_;
    const float* Vb = g_v + (size_t)(b * KH_ + kvh) * T_ * H_;
    const int* posb = g_pos + b * T_;
    const int* segb = seg + b * T_;

    int lr = tid >> 5;          // 0..7 row group for loads
    int lc = (tid & 31) << 2;   // 0..124 col (x4)

    // Load Q tile (128 rows) via cp.async
#pragma unroll
    for (int i = 0; i < 16; i++) {
        int r = lr + i * 8;
        cpa16(smem_base + (SQ_OFF + r * 132 + lc) * 4,
              Qb + (size_t)(t0 + r) * H_ + lc);
    }
    cpa_commit();

    if (tid < 128) {
        sM[tid] = -3.0e38f; sL[tid] = 0.0f;
        sPT[tid] = posb[t0 + tid];
        sST[tid] = segb[t0 + tid];
    }

    int rbase = wm * 32 + g;
    int row2 = tid >> 1, part = tid & 1;   // softmax: 2 threads/row, 32 cols each

    float cO[2][8][4];
#pragma unroll
    for (int mt = 0; mt < 2; mt++)
#pragma unroll
        for (int i = 0; i < 8; i++)
#pragma unroll
            for (int j = 0; j < 4; j++) cO[mt][i][j] = 0.0f;

    int numjt = 2 * itile + 2;
    for (int jt = 0; jt < numjt; jt++) {
        int s0 = jt * 64;

        // load K, V tiles via cp.async (single buffer)
#pragma unroll
        for (int i = 0; i < 8; i++) {
            int r = lr + i * 8;
            cpa16(smem_base + (SK_OFF + r * 132 + lc) * 4,
                  Kb + (size_t)(s0 + r) * H_ + lc);
            cpa16(smem_base + (SV_OFF + r * 136 + lc) * 4,
                  Vb + (size_t)(s0 + r) * H_ + lc);
        }
        cpa_commit();
        if (tid < 64) {
            sPS[tid] = posb[s0 + tid];
            sSG[tid] = segb[s0 + tid];
        }
        cpa_wait0();
        __syncthreads();

        // ---- S = Q K^T  (128 x 64) ----
        float cS[2][4][4];
#pragma unroll
        for (int mt = 0; mt < 2; mt++)
#pragma unroll
            for (int nt = 0; nt < 4; nt++)
#pragma unroll
                for (int j = 0; j < 4; j++) cS[mt][nt][j] = 0.0f;

#pragma unroll
        for (int k0 = 0; k0 < 128; k0 += 8) {
            uint32_t a[2][4];
#pragma unroll
            for (int mt = 0; mt < 2; mt++) {
                int r0 = rbase + mt * 16;
                a[mt][0] = sQ[r0 * 132 + k0 + qd];
                a[mt][1] = sQ[(r0 + 8) * 132 + k0 + qd];
                a[mt][2] = sQ[r0 * 132 + k0 + 4 + qd];
                a[mt][3] = sQ[(r0 + 8) * 132 + k0 + 4 + qd];
            }
            uint32_t bb[4][2];
#pragma unroll
            for (int nt = 0; nt < 4; nt++) {
                int bc = wn * 32 + nt * 8 + g;
                bb[nt][0] = sK[bc * 132 + k0 + qd];
                bb[nt][1] = sK[bc * 132 + k0 + 4 + qd];
            }
#pragma unroll
            for (int mt = 0; mt < 2; mt++)
#pragma unroll
                for (int nt = 0; nt < 4; nt++)
                    mma_tf32(cS[mt][nt], a[mt][0], a[mt][1], a[mt][2], a[mt][3],
                             bb[nt][0], bb[nt][1]);
        }

        // mask + scale -> sS
#pragma unroll
        for (int mt = 0; mt < 2; mt++) {
            int r0 = rbase + mt * 16;
            int r1 = r0 + 8;
            int pt0 = sPT[r0], st0 = sST[r0];
            int pt1 = sPT[r1], st1 = sST[r1];
#pragma unroll
            for (int nt = 0; nt < 4; nt++) {
                int col = wn * 32 + nt * 8 + qd * 2;
                int ps0 = sPS[col], ss0 = sSG[col];
                int ps1 = sPS[col + 1], ss1 = sSG[col + 1];
                sS[r0 * 68 + col]     = (ps0 <= pt0 && ss0 == st0) ? cS[mt][nt][0] * SCALE_ : KMASK_;
                sS[r0 * 68 + col + 1] = (ps1 <= pt0 && ss1 == st0) ? cS[mt][nt][1] * SCALE_ : KMASK_;
                sS[r1 * 68 + col]     = (ps0 <= pt1 && ss0 == st1) ? cS[mt][nt][2] * SCALE_ : KMASK_;
                sS[r1 * 68 + col + 1] = (ps1 <= pt1 && ss1 == st1) ? cS[mt][nt][3] * SCALE_ : KMASK_;
            }
        }
        __syncthreads();

        // ---- online softmax (2 threads per row, 32 cols each) ----
        {
            float m_old = sM[row2];
            float vals[32];
            float mx = KMASK_;
#pragma unroll
            for (int c = 0; c < 32; c++) {
                vals[c] = sS[row2 * 68 + part * 32 + c];
                mx = fmaxf(mx, vals[c]);
            }
            mx = fmaxf(mx, __shfl_xor_sync(0xffffffffu, mx, 1));
            float m_new = fmaxf(m_old, mx);
            float sum = 0.0f;
#pragma unroll
            for (int c = 0; c < 32; c++) {
                float pv = __expf(vals[c] - m_new);
                sum += pv;
                sSu[row2 * 68 + part * 32 + c] = f2tf32(pv);
            }
            sum += __shfl_xor_sync(0xffffffffu, sum, 1);
            if (part == 0) {
                float f = __expf(m_old - m_new);
                sL[row2] = sL[row2] * f + sum;
                sM[row2] = m_new;
                sF[row2] = f;
            }
        }
        __syncthreads();

        // ---- O = O*f + P V ----
#pragma unroll
        for (int mt = 0; mt < 2; mt++) {
            int r0 = rbase + mt * 16;
            float f0 = sF[r0], f1 = sF[r0 + 8];
#pragma unroll
            for (int nt = 0; nt < 8; nt++) {
                cO[mt][nt][0] *= f0; cO[mt][nt][1] *= f0;
                cO[mt][nt][2] *= f1; cO[mt][nt][3] *= f1;
            }
        }
#pragma unroll
        for (int k0 = 0; k0 < 64; k0 += 8) {
            uint32_t a[2][4];
#pragma unroll
            for (int mt = 0; mt < 2; mt++) {
                int r0 = rbase + mt * 16;
                a[mt][0] = sSu[r0 * 68 + k0 + qd];
                a[mt][1] = sSu[(r0 + 8) * 68 + k0 + qd];
                a[mt][2] = sSu[r0 * 68 + k0 + 4 + qd];
                a[mt][3] = sSu[(r0 + 8) * 68 + k0 + 4 + qd];
            }
#pragma unroll
            for (int nt = 0; nt < 8; nt++) {
                int vc = wn * 64 + nt * 8 + g;
                uint32_t b0 = sV[(k0 + qd) * 136 + vc];
                uint32_t b1 = sV[(k0 + 4 + qd) * 136 + vc];
#pragma unroll
                for (int mt = 0; mt < 2; mt++)
                    mma_tf32(cO[mt][nt], a[mt][0], a[mt][1], a[mt][2], a[mt][3],
                             b0, b1);
            }
        }
        __syncthreads();
    }

    // normalize + store (tf32-rounded for the out-projection)
#pragma unroll
    for (int mt = 0; mt < 2; mt++) {
        int r0 = rbase + mt * 16;
        int r1 = r0 + 8;
        float inv0 = 1.0f / sL[r0];
        float inv1 = 1.0f / sL[r1];
#pragma unroll
        for (int nt = 0; nt < 8; nt++) {
            int col = wn * 64 + nt * 8 + qd * 2;
            float* d0 = g_o + ((size_t)(b * T_ + t0 + r0) * NH_ + n) * H_ + col;
            float* d1 = g_o + ((size_t)(b * T_ + t0 + r1) * NH_ + n) * H_ + col;
            *(float2*)d0 = make_float2(__uint_as_float(f2tf32(cO[mt][nt][0] * inv0)),
                                       __uint_as_float(f2tf32(cO[mt][nt][1] * inv0)));
            *(float2*)d1 = make_float2(__uint_as_float(f2tf32(cO[mt][nt][2] * inv1)),
                                       __uint_as_float(f2tf32(cO[mt][nt][3] * inv1)));
        }
    }
}

// ---------------------------------------------------------------------------
// Output projection (tf32 mma, cp.async 2-stage).
// ---------------------------------------------------------------------------
__global__ __launch_bounds__(256) void sgemm_out(float* __restrict__ out) {
    extern __shared__ uint32_t smg[];
    uint32_t* sA = smg;
    uint32_t* sB = smg + GEMM_SA_WORDS;

    int tid = threadIdx.x;
    int warp = tid >> 5, lane = tid & 31;
    int g = lane >> 2, qd = lane & 3;
    int wm = warp & 1, wn = warp >> 1;

    int cn = blockIdx.x * 128;
    int rm = blockIdx.y * 128;

    uint32_t sA_base = (uint32_t)__cvta_generic_to_shared(sA);
    uint32_t sB_base = (uint32_t)__cvta_generic_to_shared(sB);

    int arA = tid >> 3, acA = (tid & 7) << 2;
    int arB = tid >> 5, acB = (tid & 31) << 2;

    float c[4][4][4];
#pragma unroll
    for (int mt = 0; mt < 4; mt++)
#pragma unroll
        for (int nt = 0; nt < 4; nt++)
#pragma unroll
            for (int i = 0; i < 4; i++) c[mt][nt][i] = 0.0f;

    auto load_stage = [&](int kk, int st) {
#pragma unroll
        for (int i = 0; i < 4; i++) {
            int r = arA + i * 32;
            cpa16(sA_base + (st * 128 * 36 + r * 36 + acA) * 4,
                  g_o + (size_t)(rm + r) * (NH_ * H_) + kk + acA);
        }
#pragma unroll
        for (int i = 0; i < 4; i++) {
            int r = arB + i * 8;
            cpa16(sB_base + (st * 32 * 136 + r * 136 + acB) * 4,
                  g_wo + (size_t)(kk + r) * D_ + cn + acB);
        }
        cpa_commit();
    };

    load_stage(0, 0);

    const int KT = (NH_ * H_) / 32;
    for (int kt = 0; kt < KT; kt++) {
        if (kt + 1 < KT) load_stage((kt + 1) * 32, (kt + 1) & 1);
        if (kt + 1 < KT) cpa_wait1(); else cpa_wait0();
        __syncthreads();

        const uint32_t* A  = sA + (kt & 1) * 128 * 36;
        const uint32_t* Bm = sB + (kt & 1) * 32 * 136;
#pragma unroll
        for (int ks = 0; ks < 4; ks++) {
            int k0 = ks * 8;
            uint32_t a[4][4];
#pragma unroll
            for (int mt = 0; mt < 4; mt++) {
                int ar = wm * 64 + mt * 16 + g;
                a[mt][0] = A[ar * 36 + k0 + qd];
                a[mt][1] = A[(ar + 8) * 36 + k0 + qd];
                a[mt][2] = A[ar * 36 + k0 + 4 + qd];
                a[mt][3] = A[(ar + 8) * 36 + k0 + 4 + qd];
            }
            uint32_t b[4][2];
#pragma unroll
            for (int nt = 0; nt < 4; nt++) {
                int bc = wn * 32 + nt * 8 + g;
                b[nt][0] = Bm[(k0 + qd) * 136 + bc];
                b[nt][1] = Bm[(k0 + 4 + qd) * 136 + bc];
            }
#pragma unroll
            for (int mt = 0; mt < 4; mt++)
#pragma unroll
                for (int nt = 0; nt < 4; nt++)
                    mma_tf32(c[mt][nt], a[mt][0], a[mt][1], a[mt][2], a[mt][3],
                             b[nt][0], b[nt][1]);
        }
        __syncthreads();
    }

#pragma unroll
    for (int mt = 0; mt < 4; mt++) {
#pragma unroll
        for (int nt = 0; nt < 4; nt++) {
            int col = cn + wn * 32 + nt * 8 + qd * 2;
            int rr0 = rm + wm * 64 + mt * 16 + g;
            int rr1 = rr0 + 8;
            *(float2*)(out + (size_t)rr0 * D_ + col) = make_float2(c[mt][nt][0], c[mt][nt][1]);
            *(float2*)(out + (size_t)rr1 * D_ + col) = make_float2(c[mt][nt][2], c[mt][nt][3]);
        }
    }
}

// ---------------------------------------------------------------------------
extern "C" void kernel_launch(void* const* d_in, const int* in_sizes, int n_in,
                              void* d_out, int out_size) {
    const float* x  = (const float*)d_in[0];
    const int*   sg = (const int*)d_in[1];
    const float* wq = (const float*)d_in[2];
    const float* wk = (const float*)d_in[3];
    const float* wv = (const float*)d_in[4];
    const float* wo = (const float*)d_in[5];
    const float* qs = (const float*)d_in[6];
    const float* ks = (const float*)d_in[7];
    float* out = (float*)d_out;

    cudaFuncSetAttribute(sgemm_qkv, cudaFuncAttributeMaxDynamicSharedMemorySize,
                         GEMM_SMEM_BYTES);
    cudaFuncSetAttribute(sgemm_out, cudaFuncAttributeMaxDynamicSharedMemorySize,
                         GEMM_SMEM_BYTES);
    cudaFuncSetAttribute(attn_kernel, cudaFuncAttributeMaxDynamicSharedMemorySize,
                         ATTN_SMEM_WORDS * 4);

    pos_kernel<<<B_, 256>>>(sg);                                        // 1
    round_x_kernel<<<512, 256>>>(x);                                    // 2
    round_w_kernel<<<512, 256>>>(wq, wk, wv, wo);                       // 3
    sgemm_qkv<<<dim3(32, 32), 256, GEMM_SMEM_BYTES>>>();                // 4
    norm_rope_kernel<<<(B_ * (NH_ + KH_) * T_) / 8, 256>>>(qs, ks);     // 5
    attn_kernel<<<B_ * NH_ * 16, 256, ATTN_SMEM_WORDS * 4>>>(sg);       // 6
    sgemm_out<<<dim3(8, 32), 256, GEMM_SMEM_BYTES>>>(out);              // 7
}